// round 11
// baseline (speedup 1.0000x reference)
#include <cuda_runtime.h>
#include <cstdint>

// LMN layer, round 11: step restructured around sync cost.
//   - flag-array barrier (one 128B line per CTA, release-store seq; waiters
//     poll 128 lines) -- removes 128-deep atomicAdd serialization.
//   - phase2 split: m' = h@Whm^T + m@Wmm^T + bm. The m@Wmm^T half runs
//     BETWEEN arrive(h) and wait(h), hiding the h-barrier behind FMA.
//   - single reduction for both phase2 GEMMs (shared accumulators).
//   - g_mT double-buffered; g_c2T eliminated.
//   - every CTA does identical work (8 h-cols, 8 m'-cols) -> minimal skew.
// Graph: zero_flags; transpose x; transpose m0; prologue; persistent recur.

#define T_STEPS 512
#define DIM     1024
#define STEP    (64 * 1024)
#define OUTS    ((size_t)T_STEPS * STEP)

typedef unsigned long long ull;

__device__ __align__(256) float g_xT [(size_t)T_STEPS * STEP];  // [t][i][b]
__device__ __align__(256) float g_xWT[(size_t)T_STEPS * STEP];  // [t][n][b]
__device__ __align__(256) float g_mT [2][STEP];                 // [buf][k][64]
__device__ __align__(256) float g_hT [STEP];                    // [k][64]
__device__ __align__(128) unsigned g_flags[128 * 32];           // 1 line/CTA

__device__ __forceinline__ void ffma2(ull& d, ull a, ull b) {
    asm("fma.rn.f32x2 %0, %1, %2, %0;" : "+l"(d) : "l"(a), "l"(b));
}
__device__ __forceinline__ ull addp(ull a, ull b) {
    ull r; asm("add.rn.f32x2 %0, %1, %2;" : "=l"(r) : "l"(a), "l"(b)); return r;
}
__device__ __forceinline__ ull splat(float x) {
    ull r; asm("mov.b64 %0, {%1, %1};" : "=l"(r) : "f"(x), "f"(x)); return r;
}
__device__ __forceinline__ ull packp(float lo, float hi) {
    ull r; asm("mov.b64 %0, {%1, %2};" : "=l"(r) : "f"(lo), "f"(hi)); return r;
}

// smem sizes (floats)
constexpr int WSL_F  = 8 * 1024;     // one 8-col weight slice [k][8]  32 KB
constexpr int W16_F  = 1024 * 20;    // prologue weights [k][20]       80 KB
constexpr int RED16  = 512 * 18 * 2; // BN=16 red                      72 KB
constexpr int RED8   = 256 * 18 * 2; // BN=8 red                       36 KB
constexpr int TR_F   = 8 * 66;

// ---------------------------------------------------------------------------
// GEMM accumulate: C[row,col] += sum_k A[row,k] * W[col,k] (no smem, no sync)
// AT k-major [k][64] in GLOBAL. 1024 thr = 32 warps = 16 kg x 2 col-halves.
// Per-thread: 4 rows (lane&15) x C=BN/4 cols; f32x2 acc over row pairs.
// Depth-2 A LDG prefetch, depth-1 W LDS prefetch, pointer walks.
// ---------------------------------------------------------------------------
template<int BN, int WP>
__device__ __forceinline__ void gemm_acc(const float* __restrict__ AT,
                                         const float* __restrict__ wT,
                                         ull (&acc)[2][BN / 4])
{
    constexpr int C = BN / 4;
    const int tid  = threadIdx.x;
    const int wid  = tid >> 5;
    const int kg   = wid & 15;
    const int ch   = wid >> 4;
    const int lane = tid & 31;
    const int ro   = lane & 15;
    const int cw   = lane >> 4;
    const int c0   = ch * (BN / 2) + cw * C;
    const int kb   = kg << 6;

    const ulonglong2* pA = (const ulonglong2*)AT + (size_t)kb * 16 + ro;
    const float* pW      = wT + (size_t)kb * WP + c0;

    ulonglong2 aP[2], aQ[2];
    aP[0] = pA[0];  aQ[0] = pA[16];
    aP[1] = pA[32]; aQ[1] = pA[48];

    float4 wb4[2]; float2 wb2[2];
    if constexpr (C == 4) {
        wb4[0] = *(const float4*)pW; wb4[1] = *(const float4*)(pW + WP);
    } else {
        wb2[0] = *(const float2*)pW; wb2[1] = *(const float2*)(pW + WP);
    }

    const ulonglong2* pApf = pA + 64;
    const float*      pWpf = pW + 2 * WP;

    #pragma unroll 4
    for (int i = 0; i < 32; ++i) {
        const int ib = i & 1;
        #pragma unroll
        for (int kk = 0; kk < 2; ++kk) {
            const ulonglong2 a = kk ? aQ[ib] : aP[ib];
            if constexpr (C == 4) {
                const float4 w4 = wb4[kk];
                ull s0 = splat(w4.x), s1 = splat(w4.y);
                ull s2 = splat(w4.z), s3 = splat(w4.w);
                ffma2(acc[0][0], a.x, s0); ffma2(acc[1][0], a.y, s0);
                ffma2(acc[0][1], a.x, s1); ffma2(acc[1][1], a.y, s1);
                ffma2(acc[0][2], a.x, s2); ffma2(acc[1][2], a.y, s2);
                ffma2(acc[0][3], a.x, s3); ffma2(acc[1][3], a.y, s3);
            } else {
                const float2 w2 = wb2[kk];
                ull s0 = splat(w2.x), s1 = splat(w2.y);
                ffma2(acc[0][0], a.x, s0); ffma2(acc[1][0], a.y, s0);
                ffma2(acc[0][1], a.x, s1); ffma2(acc[1][1], a.y, s1);
            }
        }
        if (i < 31) {
            if constexpr (C == 4) {
                wb4[0] = *(const float4*)pWpf; wb4[1] = *(const float4*)(pWpf + WP);
            } else {
                wb2[0] = *(const float2*)pWpf; wb2[1] = *(const float2*)(pWpf + WP);
            }
            pWpf += 2 * WP;
        }
        if (i < 30) {
            aP[ib] = pApf[0]; aQ[ib] = pApf[16];
            pApf += 32;
        }
    }
}

// cross-k-group reduction + epilogue; BOUNDED by syncthreads both sides
template<int BN, class Epi>
__device__ __forceinline__ void reduce_epi(ull (&acc)[2][BN / 4],
                                           float* __restrict__ redsm, Epi epi)
{
    constexpr int C = BN / 4;
    const int tid  = threadIdx.x;
    const int wid  = tid >> 5;
    const int kg   = wid & 15;
    const int ch   = wid >> 4;
    const int lane = tid & 31;
    const int ro   = lane & 15;
    const int cw   = lane >> 4;
    const int c0   = ch * (BN / 2) + cw * C;

    ull* redu = (ull*)redsm;
    const int slot = (kg + ro + cw) & 15;
    #pragma unroll
    for (int rp = 0; rp < 2; ++rp)
        #pragma unroll
        for (int c = 0; c < C; ++c)
            redu[(size_t)((c0 + c) * 32 + 2 * ro + rp) * 18 + slot] = acc[rp][c];
    __syncthreads();

    if (wid < BN) {
        const ulonglong2* r2 =
            (const ulonglong2*)(redu + (size_t)(wid * 32 + lane) * 18);
        ulonglong2 v0 = r2[0], v1 = r2[1], v2 = r2[2], v3 = r2[3];
        ulonglong2 v4 = r2[4], v5 = r2[5], v6 = r2[6], v7 = r2[7];
        ull s = addp(addp(addp(addp(v0.x, v0.y), addp(v1.x, v1.y)),
                          addp(addp(v2.x, v2.y), addp(v3.x, v3.y))),
                     addp(addp(addp(v4.x, v4.y), addp(v5.x, v5.y)),
                          addp(addp(v6.x, v6.y), addp(v7.x, v7.y))));
        epi(wid, lane, s);
    }
    __syncthreads();
}

// ---------------- flag-array barrier (128 co-resident CTAs) -----------------
// arrive: all CTA writes done -> release-store seq into this CTA's line.
// wait:   threads 0..127 each poll one CTA's line until >= seq.
__device__ __forceinline__ void bar_arrive_seq(int b, unsigned seq)
{
    __syncthreads();
    __threadfence();
    if (threadIdx.x == 0)
        asm volatile("st.release.gpu.u32 [%0], %1;"
                     :: "l"(g_flags + (size_t)b * 32), "r"(seq) : "memory");
}
__device__ __forceinline__ void bar_wait_seq(unsigned seq)
{
    if (threadIdx.x < 128) {
        const unsigned* p = g_flags + (size_t)threadIdx.x * 32;
        unsigned v;
        do {
            asm volatile("ld.acquire.gpu.u32 %0, [%1];" : "=r"(v) : "l"(p));
        } while ((int)(v - seq) < 0);
    }
    __syncthreads();
}

__global__ void zero_flags_k() {
    if (threadIdx.x < 128) g_flags[(size_t)threadIdx.x * 32] = 0u;
}

// ---------------- 64x64-tile transpose: dst[t][i][b] = src[t][b][i] ---------
__global__ void __launch_bounds__(256) transpose_k(const float* __restrict__ src,
                                                   float* __restrict__ dst)
{
    __shared__ float sm[64 * 65];
    const int t = blockIdx.y, i0 = blockIdx.x * 64, tid = threadIdx.x;
    const float* s = src + (size_t)t * STEP;
    float* d       = dst + (size_t)t * STEP;
    #pragma unroll
    for (int j = 0; j < 16; ++j) {
        int e = j * 256 + tid, b = e >> 6, i = e & 63;
        sm[b * 65 + i] = s[(size_t)b * DIM + i0 + i];
    }
    __syncthreads();
    #pragma unroll
    for (int j = 0; j < 16; ++j) {
        int e = j * 256 + tid, i = e >> 6, b = e & 63;
        d[(size_t)(i0 + i) * 64 + b] = sm[b * 65 + i];
    }
}

// ---------------- prologue: g_xWT[t] = (x[t] @ Wxh^T + bh)^T ----------------
__global__ void __launch_bounds__(1024, 1) prologue_k(const float* __restrict__ Wxh,
                                                      const float* __restrict__ bh)
{
    extern __shared__ float sm[];
    float* w1  = sm;
    float* red = sm + W16_F;
    const int cx = blockIdx.x, tid = threadIdx.x;
    for (int e = tid; e < 16 * DIM; e += 1024) {
        int c = e >> 10, k = e & 1023;
        w1[k * 20 + c] = Wxh[(size_t)(cx * 16 + c) * DIM + k];
    }
    __syncthreads();
    const int nb = cx * 16;
    #pragma unroll 1
    for (int i = 0; i < 8; ++i) {
        int t = blockIdx.y * 8 + i;
        const float* AT = g_xT + (size_t)t * STEP;
        float* xo       = g_xWT + (size_t)t * STEP;
        ull acc[2][4];
        #pragma unroll
        for (int rp = 0; rp < 2; ++rp)
            #pragma unroll
            for (int c = 0; c < 4; ++c) acc[rp][c] = 0ull;
        gemm_acc<16, 20>(AT, w1, acc);
        reduce_epi<16>(acc, red, [&](int w, int l, ull s) {
            int n = nb + w;
            *(ull*)(xo + (size_t)n * 64 + 2 * l) = addp(s, splat(bh[n]));
        });
    }
}

// ---------------- persistent recurrence ------------------------------------
// per step t (all 128 CTAs identical, 8 cols each):
//   ph1 : h[:,nb..] = tanh(xW[t] + m_cur@Wmh^T)  -> g_hT
//   arrive(2t+1)
//   ph2a: acc  = m_cur@Wmm^T           (independent of h -> hides h-barrier)
//   wait(2t+1)
//   ph2b: acc += h@Whm^T; reduce; +bm  -> g_mT[nxt] + trsm
//   arrive(2t+2); out[t] store + xW prefetch overlap; wait(2t+2)
__global__ void __launch_bounds__(1024, 1) recur_k(const float* __restrict__ Whm,
                                                   const float* __restrict__ Wmm,
                                                   const float* __restrict__ Wmh,
                                                   const float* __restrict__ bm,
                                                   float* __restrict__ out)
{
    extern __shared__ float sm[];
    float* wmh  = sm;                       // [k][8]
    float* wmm  = sm + WSL_F;               // [k][8]
    float* whm  = sm + 2 * WSL_F;           // [k][8]
    float* red  = sm + 3 * WSL_F;
    float* trsm = sm + 3 * WSL_F + RED8;    // [8][66]
    const int b = blockIdx.x, tid = threadIdx.x;
    const int wid = tid >> 5, lane = tid & 31;
    const int nb = b * 8;

    for (int e = tid; e < 8 * DIM; e += 1024) {
        int c = e >> 10, k = e & 1023;
        wmh[k * 8 + c] = Wmh[(size_t)(nb + c) * DIM + k];
        wmm[k * 8 + c] = Wmm[(size_t)(nb + c) * DIM + k];
        whm[k * 8 + c] = Whm[(size_t)(nb + c) * DIM + k];
    }
    __syncthreads();

    ull bmsp = 0;
    if (wid < 8) bmsp = splat(bm[nb + wid]);
    ull xwbuf = 0;
    if (wid < 8)
        xwbuf = *(const ull*)(g_xWT + (size_t)(nb + wid) * 64 + 2 * lane);

    #pragma unroll 1
    for (int t = 0; t < T_STEPS; ++t) {
        const float* mcur = g_mT[t & 1];
        float*       mnxt = g_mT[(t + 1) & 1];

        // ---- phase 1: h ----
        {
            ull acc[2][2];
            acc[0][0] = acc[0][1] = acc[1][0] = acc[1][1] = 0ull;
            gemm_acc<8, 8>(mcur, wmh, acc);
            reduce_epi<8>(acc, red, [&](int w, int l, ull s) {
                ull v = addp(s, xwbuf);
                float lo = __uint_as_float((unsigned)v);
                float hi = __uint_as_float((unsigned)(v >> 32));
                *(ull*)(g_hT + (size_t)(nb + w) * 64 + 2 * l) =
                    packp(tanhf(lo), tanhf(hi));
            });
        }
        bar_arrive_seq(b, 2 * t + 1);

        // ---- phase 2 ----
        {
            ull acc[2][2];
            acc[0][0] = acc[0][1] = acc[1][0] = acc[1][1] = 0ull;
            gemm_acc<8, 8>(mcur, wmm, acc);     // overlaps the h-barrier
            bar_wait_seq(2 * t + 1);
            gemm_acc<8, 8>(g_hT, whm, acc);
            reduce_epi<8>(acc, red, [&](int w, int l, ull s) {
                ull v = addp(s, bmsp);
                *(ull*)(mnxt + (size_t)(nb + w) * 64 + 2 * l) = v;
                *(ull*)(trsm + w * 66 + 2 * l) = v;
            });
        }
        bar_arrive_seq(b, 2 * t + 2);

        // overlap out store + next xW prefetch with the m'-wait
        if (tid < 512) {
            int bb = tid >> 3, c = tid & 7;
            float v = trsm[c * 66 + bb];
            out[(size_t)t * STEP + (size_t)bb * DIM + nb + c] = v;
            if (t == T_STEPS - 1)
                out[OUTS + (size_t)bb * DIM + nb + c] = v;      // m_final
        }
        if (wid < 8 && t + 1 < T_STEPS)
            xwbuf = *(const ull*)(g_xWT + (size_t)(t + 1) * STEP
                                  + (size_t)(nb + wid) * 64 + 2 * lane);
        bar_wait_seq(2 * t + 2);
    }
}

#define PRO_SMEM ((W16_F + RED16) * 4)                  // 155648 B
#define PER_SMEM ((3 * WSL_F + RED8 + TR_F) * 4)        // 137280 B

extern "C" void kernel_launch(void* const* d_in, const int* in_sizes, int n_in,
                              void* d_out, int out_size)
{
    const float* x      = (const float*)d_in[0];
    const float* m_prev = (const float*)d_in[1];
    const float* Wxh    = (const float*)d_in[2];
    const float* Whm    = (const float*)d_in[3];
    const float* Wmm    = (const float*)d_in[4];
    const float* Wmh    = (const float*)d_in[5];
    const float* bh     = (const float*)d_in[6];
    const float* bm     = (const float*)d_in[7];
    float* out = (float*)d_out;

    cudaFuncSetAttribute(prologue_k,
                         cudaFuncAttributeMaxDynamicSharedMemorySize, PRO_SMEM);
    cudaFuncSetAttribute(recur_k,
                         cudaFuncAttributeMaxDynamicSharedMemorySize, PER_SMEM);

    float* d_gxT; cudaGetSymbolAddress((void**)&d_gxT, g_xT);
    float* d_gmT; cudaGetSymbolAddress((void**)&d_gmT, g_mT);  // buffer 0

    zero_flags_k<<<1, 128>>>();
    transpose_k<<<dim3(16, 512), 256>>>(x, d_gxT);          // x  -> g_xT
    transpose_k<<<dim3(16, 1), 256>>>(m_prev, d_gmT);       // m0 -> g_mT[0]
    prologue_k<<<dim3(64, 64), 1024, PRO_SMEM>>>(Wxh, bh);
    recur_k<<<128, 1024, PER_SMEM>>>(Whm, Wmm, Wmh, bm, out);
}

// round 12
// speedup vs baseline: 1.1430x; 1.1430x over previous
#include <cuda_runtime.h>
#include <cstdint>

// LMN layer, round 12: fused phase-1 (h + c2 in ONE BN=16 A-pass), c2 kept in
// CTA-local smem, flag-array barrier with nanosleep backoff.
//   per step t (all 128 CTAs identical, 8 output cols each):
//     ph1 : [h | c2] = m @ [Wmh | Wmm]^T   (BN=16, A read once)
//           h-cols -> tanh(xW+.) -> g_hT ; c2-cols -> smem c2b
//     arrive(2t+1); wait(2t+1)
//     ph2 : m' = h@Whm^T + c2b + bm        (BN=8)  -> g_mT + trsm
//     arrive(2t+2); out[t] store + xW prefetch overlap; wait(2t+2)
// A-LDG per CTA per step = 512 KB total (the LSU 4-cyc/LDG floor is the
// binding pipe; round 11's 768 KB was the regression).

#define T_STEPS 512
#define DIM     1024
#define STEP    (64 * 1024)
#define OUTS    ((size_t)T_STEPS * STEP)

typedef unsigned long long ull;

__device__ __align__(256) float g_xT [(size_t)T_STEPS * STEP];  // [t][i][b]
__device__ __align__(256) float g_xWT[(size_t)T_STEPS * STEP];  // [t][n][b]
__device__ __align__(256) float g_mT [STEP];                    // [k][64]
__device__ __align__(256) float g_hT [STEP];                    // [k][64]
__device__ __align__(128) unsigned g_flags[128 * 32];           // 1 line/CTA

__device__ __forceinline__ void ffma2(ull& d, ull a, ull b) {
    asm("fma.rn.f32x2 %0, %1, %2, %0;" : "+l"(d) : "l"(a), "l"(b));
}
__device__ __forceinline__ ull addp(ull a, ull b) {
    ull r; asm("add.rn.f32x2 %0, %1, %2;" : "=l"(r) : "l"(a), "l"(b)); return r;
}
__device__ __forceinline__ ull splat(float x) {
    ull r; asm("mov.b64 %0, {%1, %1};" : "=l"(r) : "f"(x), "f"(x)); return r;
}
__device__ __forceinline__ ull packp(float lo, float hi) {
    ull r; asm("mov.b64 %0, {%1, %2};" : "=l"(r) : "f"(lo), "f"(hi)); return r;
}

// smem sizes (floats)
constexpr int WPH1_F = 16 * 1024;    // fused [k][16] = [Wmh 8 | Wmm 8]  64 KB
constexpr int WHM_F  = 8 * 1024;     // whm [k][8]                      32 KB
constexpr int RED16  = 512 * 18 * 2; // BN=16 reduction                 72 KB
constexpr int C2_F   = 8 * 33 * 2;   // c2b: 8 cols x 33-ull stride
constexpr int TR_F   = 8 * 66;       // out-transpose tile
constexpr int W16_F  = 1024 * 20;    // prologue weights [k][20]        80 KB

// ---------------------------------------------------------------------------
// GEMM accumulate: C[row,col] += sum_k A[row,k] * W[col,k] (no smem, no sync)
// AT k-major [k][64] in GLOBAL. 1024 thr = 32 warps = 16 kg x 2 col-halves.
// Per-thread: 4 rows (lane&15) x C=BN/4 cols; f32x2 acc over row pairs.
// Depth-2 A LDG prefetch, depth-1 W LDS prefetch, pointer walks.
// ---------------------------------------------------------------------------
template<int BN, int WP>
__device__ __forceinline__ void gemm_acc(const float* __restrict__ AT,
                                         const float* __restrict__ wT,
                                         ull (&acc)[2][BN / 4])
{
    constexpr int C = BN / 4;
    const int tid  = threadIdx.x;
    const int wid  = tid >> 5;
    const int kg   = wid & 15;
    const int ch   = wid >> 4;
    const int lane = tid & 31;
    const int ro   = lane & 15;
    const int cw   = lane >> 4;
    const int c0   = ch * (BN / 2) + cw * C;
    const int kb   = kg << 6;

    const ulonglong2* pA = (const ulonglong2*)AT + (size_t)kb * 16 + ro;
    const float* pW      = wT + (size_t)kb * WP + c0;

    ulonglong2 aP[2], aQ[2];
    aP[0] = pA[0];  aQ[0] = pA[16];
    aP[1] = pA[32]; aQ[1] = pA[48];

    float4 wb4[2]; float2 wb2[2];
    if constexpr (C == 4) {
        wb4[0] = *(const float4*)pW; wb4[1] = *(const float4*)(pW + WP);
    } else {
        wb2[0] = *(const float2*)pW; wb2[1] = *(const float2*)(pW + WP);
    }

    const ulonglong2* pApf = pA + 64;
    const float*      pWpf = pW + 2 * WP;

    #pragma unroll 4
    for (int i = 0; i < 32; ++i) {
        const int ib = i & 1;
        #pragma unroll
        for (int kk = 0; kk < 2; ++kk) {
            const ulonglong2 a = kk ? aQ[ib] : aP[ib];
            if constexpr (C == 4) {
                const float4 w4 = wb4[kk];
                ull s0 = splat(w4.x), s1 = splat(w4.y);
                ull s2 = splat(w4.z), s3 = splat(w4.w);
                ffma2(acc[0][0], a.x, s0); ffma2(acc[1][0], a.y, s0);
                ffma2(acc[0][1], a.x, s1); ffma2(acc[1][1], a.y, s1);
                ffma2(acc[0][2], a.x, s2); ffma2(acc[1][2], a.y, s2);
                ffma2(acc[0][3], a.x, s3); ffma2(acc[1][3], a.y, s3);
            } else {
                const float2 w2 = wb2[kk];
                ull s0 = splat(w2.x), s1 = splat(w2.y);
                ffma2(acc[0][0], a.x, s0); ffma2(acc[1][0], a.y, s0);
                ffma2(acc[0][1], a.x, s1); ffma2(acc[1][1], a.y, s1);
            }
        }
        if (i < 31) {
            if constexpr (C == 4) {
                wb4[0] = *(const float4*)pWpf; wb4[1] = *(const float4*)(pWpf + WP);
            } else {
                wb2[0] = *(const float2*)pWpf; wb2[1] = *(const float2*)(pWpf + WP);
            }
            pWpf += 2 * WP;
        }
        if (i < 30) {
            aP[ib] = pApf[0]; aQ[ib] = pApf[16];
            pApf += 32;
        }
    }
}

// cross-k-group reduction + epilogue; bounded by syncthreads both sides
template<int BN, class Epi>
__device__ __forceinline__ void reduce_epi(ull (&acc)[2][BN / 4],
                                           float* __restrict__ redsm, Epi epi)
{
    constexpr int C = BN / 4;
    const int tid  = threadIdx.x;
    const int wid  = tid >> 5;
    const int kg   = wid & 15;
    const int ch   = wid >> 4;
    const int lane = tid & 31;
    const int ro   = lane & 15;
    const int cw   = lane >> 4;
    const int c0   = ch * (BN / 2) + cw * C;

    ull* redu = (ull*)redsm;
    const int slot = (kg + ro + cw) & 15;
    #pragma unroll
    for (int rp = 0; rp < 2; ++rp)
        #pragma unroll
        for (int c = 0; c < C; ++c)
            redu[(size_t)((c0 + c) * 32 + 2 * ro + rp) * 18 + slot] = acc[rp][c];
    __syncthreads();

    if (wid < BN) {
        const ulonglong2* r2 =
            (const ulonglong2*)(redu + (size_t)(wid * 32 + lane) * 18);
        ulonglong2 v0 = r2[0], v1 = r2[1], v2 = r2[2], v3 = r2[3];
        ulonglong2 v4 = r2[4], v5 = r2[5], v6 = r2[6], v7 = r2[7];
        ull s = addp(addp(addp(addp(v0.x, v0.y), addp(v1.x, v1.y)),
                          addp(addp(v2.x, v2.y), addp(v3.x, v3.y))),
                     addp(addp(addp(v4.x, v4.y), addp(v5.x, v5.y)),
                          addp(addp(v6.x, v6.y), addp(v7.x, v7.y))));
        epi(wid, lane, s);
    }
    __syncthreads();
}

// ---------------- flag-array barrier (128 co-resident CTAs) -----------------
__device__ __forceinline__ void bar_arrive_seq(int b, unsigned seq)
{
    __syncthreads();
    __threadfence();
    if (threadIdx.x == 0)
        asm volatile("st.release.gpu.u32 [%0], %1;"
                     :: "l"(g_flags + (size_t)b * 32), "r"(seq) : "memory");
}
__device__ __forceinline__ void bar_wait_seq(unsigned seq)
{
    if (threadIdx.x < 128) {
        const unsigned* p = g_flags + (size_t)threadIdx.x * 32;
        unsigned v;
        asm volatile("ld.acquire.gpu.u32 %0, [%1];" : "=r"(v) : "l"(p));
        while ((int)(v - seq) < 0) {
            __nanosleep(64);               // keep pollers off the L2
            asm volatile("ld.acquire.gpu.u32 %0, [%1];" : "=r"(v) : "l"(p));
        }
    }
    __syncthreads();
}

__global__ void zero_flags_k() {
    if (threadIdx.x < 128) g_flags[(size_t)threadIdx.x * 32] = 0u;
}

// ---------------- 64x64-tile transpose: dst[t][i][b] = src[t][b][i] ---------
__global__ void __launch_bounds__(256) transpose_k(const float* __restrict__ src,
                                                   float* __restrict__ dst)
{
    __shared__ float sm[64 * 65];
    const int t = blockIdx.y, i0 = blockIdx.x * 64, tid = threadIdx.x;
    const float* s = src + (size_t)t * STEP;
    float* d       = dst + (size_t)t * STEP;
    #pragma unroll
    for (int j = 0; j < 16; ++j) {
        int e = j * 256 + tid, b = e >> 6, i = e & 63;
        sm[b * 65 + i] = s[(size_t)b * DIM + i0 + i];
    }
    __syncthreads();
    #pragma unroll
    for (int j = 0; j < 16; ++j) {
        int e = j * 256 + tid, i = e >> 6, b = e & 63;
        d[(size_t)(i0 + i) * 64 + b] = sm[b * 65 + i];
    }
}

// ---------------- prologue: g_xWT[t] = (x[t] @ Wxh^T + bh)^T ----------------
__global__ void __launch_bounds__(1024, 1) prologue_k(const float* __restrict__ Wxh,
                                                      const float* __restrict__ bh)
{
    extern __shared__ float sm[];
    float* w1  = sm;
    float* red = sm + W16_F;
    const int cx = blockIdx.x, tid = threadIdx.x;
    for (int e = tid; e < 16 * DIM; e += 1024) {
        int c = e >> 10, k = e & 1023;
        w1[k * 20 + c] = Wxh[(size_t)(cx * 16 + c) * DIM + k];
    }
    __syncthreads();
    const int nb = cx * 16;
    #pragma unroll 1
    for (int i = 0; i < 8; ++i) {
        int t = blockIdx.y * 8 + i;
        const float* AT = g_xT + (size_t)t * STEP;
        float* xo       = g_xWT + (size_t)t * STEP;
        ull acc[2][4];
        #pragma unroll
        for (int rp = 0; rp < 2; ++rp)
            #pragma unroll
            for (int c = 0; c < 4; ++c) acc[rp][c] = 0ull;
        gemm_acc<16, 20>(AT, w1, acc);
        reduce_epi<16>(acc, red, [&](int w, int l, ull s) {
            int n = nb + w;
            *(ull*)(xo + (size_t)n * 64 + 2 * l) = addp(s, splat(bh[n]));
        });
    }
}

// ---------------- persistent recurrence ------------------------------------
__global__ void __launch_bounds__(1024, 1) recur_k(const float* __restrict__ Whm,
                                                   const float* __restrict__ Wmm,
                                                   const float* __restrict__ Wmh,
                                                   const float* __restrict__ bm,
                                                   float* __restrict__ out)
{
    extern __shared__ float sm[];
    float* wph1 = sm;                              // [k][16] = [Wmh8|Wmm8]
    float* whm  = sm + WPH1_F;                     // [k][8]
    float* red  = sm + WPH1_F + WHM_F;
    ull*   c2b  = (ull*)(sm + WPH1_F + WHM_F + RED16);       // [8][33] ull
    float* trsm = sm + WPH1_F + WHM_F + RED16 + C2_F;        // [8][66]
    const int b = blockIdx.x, tid = threadIdx.x;
    const int wid = tid >> 5, lane = tid & 31;
    const int nb = b * 8;

    // fused phase-1 weights: cols 0-7 = Wmh slice, cols 8-15 = Wmm slice
    for (int e = tid; e < 16 * DIM; e += 1024) {
        int c = e >> 10, k = e & 1023;
        wph1[k * 16 + c] = (c < 8)
            ? Wmh[(size_t)(nb + c) * DIM + k]
            : Wmm[(size_t)(nb + c - 8) * DIM + k];
    }
    for (int e = tid; e < 8 * DIM; e += 1024) {
        int c = e >> 10, k = e & 1023;
        whm[k * 8 + c] = Whm[(size_t)(nb + c) * DIM + k];
    }
    __syncthreads();

    ull bmsp = 0;
    if (wid < 8) bmsp = splat(bm[nb + wid]);
    ull xwbuf = 0;
    if (wid < 8)
        xwbuf = *(const ull*)(g_xWT + (size_t)(nb + wid) * 64 + 2 * lane);

    #pragma unroll 1
    for (int t = 0; t < T_STEPS; ++t) {
        // ---- phase 1: [h | c2] = m @ [Wmh | Wmm]^T  (one A pass) ----
        {
            ull acc[2][4];
            #pragma unroll
            for (int rp = 0; rp < 2; ++rp)
                #pragma unroll
                for (int c = 0; c < 4; ++c) acc[rp][c] = 0ull;
            gemm_acc<16, 16>(g_mT, wph1, acc);
            reduce_epi<16>(acc, red, [&](int w, int l, ull s) {
                if (w < 8) {
                    ull v = addp(s, xwbuf);
                    float lo = __uint_as_float((unsigned)v);
                    float hi = __uint_as_float((unsigned)(v >> 32));
                    *(ull*)(g_hT + (size_t)(nb + w) * 64 + 2 * l) =
                        packp(tanhf(lo), tanhf(hi));
                } else {
                    c2b[(w - 8) * 33 + l] = s;       // stays in this CTA
                }
            });
        }
        bar_arrive_seq(b, 2 * t + 1);
        bar_wait_seq(2 * t + 1);

        // ---- phase 2: m' = h@Whm^T + c2 + bm ----
        // Writing g_mT here is safe: bar(2t+1) proved every CTA finished
        // reading m (phase 1 is its only reader).
        {
            ull acc[2][2];
            acc[0][0] = acc[0][1] = acc[1][0] = acc[1][1] = 0ull;
            gemm_acc<8, 8>(g_hT, whm, acc);
            reduce_epi<8>(acc, red, [&](int w, int l, ull s) {
                ull v = addp(addp(s, c2b[w * 33 + l]), bmsp);
                *(ull*)(g_mT + (size_t)(nb + w) * 64 + 2 * l) = v;
                *(ull*)(trsm + w * 66 + 2 * l) = v;
            });
        }
        bar_arrive_seq(b, 2 * t + 2);

        // overlap out store + next-step xW prefetch with the m'-wait
        if (tid < 512) {
            int bb = tid >> 3, c = tid & 7;
            float v = trsm[c * 66 + bb];
            out[(size_t)t * STEP + (size_t)bb * DIM + nb + c] = v;
            if (t == T_STEPS - 1)
                out[OUTS + (size_t)bb * DIM + nb + c] = v;      // m_final
        }
        if (wid < 8 && t + 1 < T_STEPS)
            xwbuf = *(const ull*)(g_xWT + (size_t)(t + 1) * STEP
                                  + (size_t)(nb + wid) * 64 + 2 * lane);
        bar_wait_seq(2 * t + 2);
    }
}

#define PRO_SMEM ((W16_F + RED16) * 4)                          // 155648 B
#define PER_SMEM ((WPH1_F + WHM_F + RED16 + C2_F + TR_F) * 4)   // 176256 B

extern "C" void kernel_launch(void* const* d_in, const int* in_sizes, int n_in,
                              void* d_out, int out_size)
{
    const float* x      = (const float*)d_in[0];
    const float* m_prev = (const float*)d_in[1];
    const float* Wxh    = (const float*)d_in[2];
    const float* Whm    = (const float*)d_in[3];
    const float* Wmm    = (const float*)d_in[4];
    const float* Wmh    = (const float*)d_in[5];
    const float* bh     = (const float*)d_in[6];
    const float* bm     = (const float*)d_in[7];
    float* out = (float*)d_out;

    cudaFuncSetAttribute(prologue_k,
                         cudaFuncAttributeMaxDynamicSharedMemorySize, PRO_SMEM);
    cudaFuncSetAttribute(recur_k,
                         cudaFuncAttributeMaxDynamicSharedMemorySize, PER_SMEM);

    float* d_gxT; cudaGetSymbolAddress((void**)&d_gxT, g_xT);
    float* d_gmT; cudaGetSymbolAddress((void**)&d_gmT, g_mT);

    zero_flags_k<<<1, 128>>>();
    transpose_k<<<dim3(16, 512), 256>>>(x, d_gxT);          // x  -> g_xT
    transpose_k<<<dim3(16, 1), 256>>>(m_prev, d_gmT);       // m0 -> g_mT
    prologue_k<<<dim3(64, 64), 1024, PRO_SMEM>>>(Wxh, bh);
    recur_k<<<128, 1024, PER_SMEM>>>(Whm, Wmm, Wmh, bm, out);
}

// round 14
// speedup vs baseline: 1.3240x; 1.1584x over previous
#include <cuda_runtime.h>
#include <cuda_bf16.h>
#include <cstdint>

// LMN layer, round 14: recurrence on mma.sync HMMA (tcgen05 unavailable —
// ptxas targets sm_103 base). Transposed GEMMs: D[feat][batch] = W @ A^T,
// bf16 2-way split (3 mma terms, fp32 accum).
//   128 persistent CTAs x 512 thr (16 warps = 8 nf x 2 k-halves):
//   phase1: CTA b: rows 16b of stacked [Wmh;Wmm] (2048), full K=1024.
//     b<64 -> h rows: +xW, tanh, repack to g_ph (B-frag layout).
//     b>=64 -> c2 rows: store fp32 g_c2.
//   bar; phase2: CTA b: Whm rows 16*(b>>1), K-half (b&1) -> g_partB.
//   bar; reduce2: 8 m'-rows/CTA: sum 2 partials + c2 + bm -> out[t] + g_pm.
//   bar.  Weights SMEM-resident pre-packed in A-frag order (LDS.128 = frag);
//   activations packed in B-frag order in global (LDG.128 = 2 frags).
// Prologue/x-transpose: proven SIMT kernels (round 12).

#define T_STEPS 512
#define DIM     1024
#define STEP    (64 * 1024)
#define OUTS    ((size_t)T_STEPS * STEP)

typedef unsigned long long ull;
typedef uint32_t u32;
typedef uint16_t u16;

__device__ __align__(256) float g_xT [(size_t)T_STEPS * STEP];  // [t][i][b]
__device__ __align__(256) float g_xWT[(size_t)T_STEPS * STEP];  // [t][n][b]
__device__ __align__(256) u32   g_pm[65536];     // m packed [s][nf][pair][lane][4]
__device__ __align__(256) u32   g_ph[65536];     // h packed, same layout
__device__ __align__(256) float g_c2[1024 * 64]; // [feat][batch]
__device__ __align__(256) float g_partB[128 * 16 * 64];
__device__ __align__(128) unsigned g_flags[128 * 32];

// ---------------- bf16 helpers ----------------------------------------------
__device__ __forceinline__ u32 b16(float x) {
    return (u32)__bfloat16_as_ushort(__float2bfloat16(x));
}
__device__ __forceinline__ float fb16(u32 b) {
    return __bfloat162float(__ushort_as_bfloat16((u16)b));
}
__device__ __forceinline__ u32 packlo(float a, float b) {   // low-order parts
    float la = a - fb16(b16(a)), lb = b - fb16(b16(b));
    return b16(la) | (b16(lb) << 16);
}
__device__ __forceinline__ u32 packhi(float a, float b) {
    return b16(a) | (b16(b) << 16);
}

// packed activation index: [s][nf][pair(32)][lane(32)][4 u32]
__device__ __forceinline__ size_t pk(int s, int nf, int pair, int lane) {
    return ((((size_t)s * 8 + nf) * 32 + pair) * 32 + lane) * 4;
}

// mma.sync m16n8k16 row.col f32.bf16.bf16.f32
__device__ __forceinline__ void mma4(float* c, const u32* a, u32 b0, u32 b1) {
    asm volatile(
        "mma.sync.aligned.m16n8k16.row.col.f32.bf16.bf16.f32 "
        "{%0,%1,%2,%3}, {%4,%5,%6,%7}, {%8,%9}, {%0,%1,%2,%3};"
        : "+f"(c[0]), "+f"(c[1]), "+f"(c[2]), "+f"(c[3])
        : "r"(a[0]), "r"(a[1]), "r"(a[2]), "r"(a[3]), "r"(b0), "r"(b1));
}

// ---------------- f32x2 helpers (SIMT prologue) ------------------------------
__device__ __forceinline__ void ffma2(ull& d, ull a, ull b) {
    asm("fma.rn.f32x2 %0, %1, %2, %0;" : "+l"(d) : "l"(a), "l"(b));
}
__device__ __forceinline__ ull addp(ull a, ull b) {
    ull r; asm("add.rn.f32x2 %0, %1, %2;" : "=l"(r) : "l"(a), "l"(b)); return r;
}
__device__ __forceinline__ ull splat(float x) {
    ull r; asm("mov.b64 %0, {%1, %1};" : "=l"(r) : "f"(x), "f"(x)); return r;
}

// ---------------- flag-array barrier (128 co-resident CTAs) -----------------
__device__ __forceinline__ void bar_arrive_seq(int b, unsigned seq)
{
    __syncthreads();
    __threadfence();
    if (threadIdx.x == 0)
        asm volatile("st.release.gpu.u32 [%0], %1;"
                     :: "l"(g_flags + (size_t)b * 32), "r"(seq) : "memory");
}
__device__ __forceinline__ void bar_wait_seq(unsigned seq)
{
    if (threadIdx.x < 128) {
        const unsigned* p = g_flags + (size_t)threadIdx.x * 32;
        unsigned v;
        asm volatile("ld.acquire.gpu.u32 %0, [%1];" : "=r"(v) : "l"(p));
        while ((int)(v - seq) < 0) {
            __nanosleep(64);
            asm volatile("ld.acquire.gpu.u32 %0, [%1];" : "=r"(v) : "l"(p));
        }
    }
    __syncthreads();
}
__global__ void zero_flags_k() {
    if (threadIdx.x < 128) g_flags[(size_t)threadIdx.x * 32] = 0u;
}

// ---------------- 64x64-tile transpose: dst[t][i][b] = src[t][b][i] ---------
__global__ void __launch_bounds__(256) transpose_k(const float* __restrict__ src,
                                                   float* __restrict__ dst)
{
    __shared__ float sm[64 * 65];
    const int t = blockIdx.y, i0 = blockIdx.x * 64, tid = threadIdx.x;
    const float* s = src + (size_t)t * STEP;
    float* d       = dst + (size_t)t * STEP;
    #pragma unroll
    for (int j = 0; j < 16; ++j) {
        int e = j * 256 + tid, b = e >> 6, i = e & 63;
        sm[b * 65 + i] = s[(size_t)b * DIM + i0 + i];
    }
    __syncthreads();
    #pragma unroll
    for (int j = 0; j < 16; ++j) {
        int e = j * 256 + tid, i = e >> 6, b = e & 63;
        d[(size_t)(i0 + i) * 64 + b] = sm[b * 65 + i];
    }
}

// ---------------- m0 -> packed B-frag layout --------------------------------
__global__ void conv_m0_k(const float* __restrict__ m_prev)
{
    int e = blockIdx.x * 512 + threadIdx.x;          // 128 blocks x 512
    int q = e & 3, lane = (e >> 2) & 31, pair = (e >> 7) & 31;
    int nf = (e >> 12) & 7, s = e >> 15;
    int kf = 2 * pair + (q >> 1), reg = q & 1;
    int kc = 16 * kf + 2 * (lane & 3) + 8 * reg;
    int n  = 8 * nf + (lane >> 2);
    float w0 = m_prev[(size_t)n * DIM + kc];
    float w1 = m_prev[(size_t)n * DIM + kc + 1];
    g_pm[e] = s ? packlo(w0, w1) : packhi(w0, w1);
}

// ---------------- SIMT GEMM core (prologue only, from round 12) -------------
constexpr int W16_F = 1024 * 20;
constexpr int RED16 = 512 * 18 * 2;

template<int BN, int WP>
__device__ __forceinline__ void gemm_acc(const float* __restrict__ AT,
                                         const float* __restrict__ wT,
                                         ull (&acc)[2][BN / 4])
{
    const int tid  = threadIdx.x;
    const int wid  = tid >> 5;
    const int kg   = wid & 15;
    const int ch   = wid >> 4;
    const int lane = tid & 31;
    const int ro   = lane & 15;
    const int cw   = lane >> 4;
    const int c0   = ch * (BN / 2) + cw * (BN / 4);
    const int kb   = kg << 6;

    const ulonglong2* pA = (const ulonglong2*)AT + (size_t)kb * 16 + ro;
    const float* pW      = wT + (size_t)kb * WP + c0;

    ulonglong2 aP[2], aQ[2];
    aP[0] = pA[0];  aQ[0] = pA[16];
    aP[1] = pA[32]; aQ[1] = pA[48];
    float4 wb4[2];
    wb4[0] = *(const float4*)pW; wb4[1] = *(const float4*)(pW + WP);

    const ulonglong2* pApf = pA + 64;
    const float*      pWpf = pW + 2 * WP;

    #pragma unroll 4
    for (int i = 0; i < 32; ++i) {
        const int ib = i & 1;
        #pragma unroll
        for (int kk = 0; kk < 2; ++kk) {
            const ulonglong2 a = kk ? aQ[ib] : aP[ib];
            const float4 w4 = wb4[kk];
            ull s0 = splat(w4.x), s1 = splat(w4.y);
            ull s2 = splat(w4.z), s3 = splat(w4.w);
            ffma2(acc[0][0], a.x, s0); ffma2(acc[1][0], a.y, s0);
            ffma2(acc[0][1], a.x, s1); ffma2(acc[1][1], a.y, s1);
            ffma2(acc[0][2], a.x, s2); ffma2(acc[1][2], a.y, s2);
            ffma2(acc[0][3], a.x, s3); ffma2(acc[1][3], a.y, s3);
        }
        if (i < 31) {
            wb4[0] = *(const float4*)pWpf; wb4[1] = *(const float4*)(pWpf + WP);
            pWpf += 2 * WP;
        }
        if (i < 30) {
            aP[ib] = pApf[0]; aQ[ib] = pApf[16];
            pApf += 32;
        }
    }
}

template<int BN, class Epi>
__device__ __forceinline__ void reduce_epi(ull (&acc)[2][BN / 4],
                                           float* __restrict__ redsm, Epi epi)
{
    constexpr int C = BN / 4;
    const int tid  = threadIdx.x;
    const int wid  = tid >> 5;
    const int kg   = wid & 15;
    const int ch   = wid >> 4;
    const int lane = tid & 31;
    const int ro   = lane & 15;
    const int cw   = lane >> 4;
    const int c0   = ch * (BN / 2) + cw * C;

    ull* redu = (ull*)redsm;
    const int slot = (kg + ro + cw) & 15;
    #pragma unroll
    for (int rp = 0; rp < 2; ++rp)
        #pragma unroll
        for (int c = 0; c < C; ++c)
            redu[(size_t)((c0 + c) * 32 + 2 * ro + rp) * 18 + slot] = acc[rp][c];
    __syncthreads();

    if (wid < BN) {
        const ulonglong2* r2 =
            (const ulonglong2*)(redu + (size_t)(wid * 32 + lane) * 18);
        ulonglong2 v0 = r2[0], v1 = r2[1], v2 = r2[2], v3 = r2[3];
        ulonglong2 v4 = r2[4], v5 = r2[5], v6 = r2[6], v7 = r2[7];
        ull s = addp(addp(addp(addp(v0.x, v0.y), addp(v1.x, v1.y)),
                          addp(addp(v2.x, v2.y), addp(v3.x, v3.y))),
                     addp(addp(addp(v4.x, v4.y), addp(v5.x, v5.y)),
                          addp(addp(v6.x, v6.y), addp(v7.x, v7.y))));
        epi(wid, lane, s);
    }
    __syncthreads();
}

__global__ void __launch_bounds__(1024, 1) prologue_k(const float* __restrict__ Wxh,
                                                      const float* __restrict__ bh)
{
    extern __shared__ float sm[];
    float* w1  = sm;
    float* red = sm + W16_F;
    const int cx = blockIdx.x, tid = threadIdx.x;
    for (int e = tid; e < 16 * DIM; e += 1024) {
        int c = e >> 10, k = e & 1023;
        w1[k * 20 + c] = Wxh[(size_t)(cx * 16 + c) * DIM + k];
    }
    __syncthreads();
    const int nb = cx * 16;
    #pragma unroll 1
    for (int i = 0; i < 8; ++i) {
        int t = blockIdx.y * 8 + i;
        const float* AT = g_xT + (size_t)t * STEP;
        float* xo       = g_xWT + (size_t)t * STEP;
        ull acc[2][4];
        #pragma unroll
        for (int rp = 0; rp < 2; ++rp)
            #pragma unroll
            for (int c = 0; c < 4; ++c) acc[rp][c] = 0ull;
        gemm_acc<16, 20>(AT, w1, acc);
        reduce_epi<16>(acc, red, [&](int w, int l, ull s) {
            int n = nb + w;
            *(ull*)(xo + (size_t)n * 64 + 2 * l) = addp(s, splat(bh[n]));
        });
    }
}

// ---------------- persistent HMMA recurrence --------------------------------
// smem (u32 units): W1H 0..8191, W1L 8192.., W2H 16384.., W2L 20480..,
// DRED f32 at 24576 (1024), RP u16 at u32 25600 (2x16x72)
#define SM_W1H 0
#define SM_W1L 8192
#define SM_W2H 16384
#define SM_W2L 20480
#define SM_DRED 24576
#define SM_RP  25600
#define TC_SMEM ((25600 + 1152) * 4)     // 107008 B

__global__ void __launch_bounds__(512, 1)
recur_k(const float* __restrict__ Whm, const float* __restrict__ Wmm,
        const float* __restrict__ Wmh, const float* __restrict__ bm,
        float* __restrict__ out)
{
    extern __shared__ u32 smu[];
    u32*   w1h  = smu + SM_W1H;
    u32*   w1l  = smu + SM_W1L;
    u32*   w2h  = smu + SM_W2H;
    u32*   w2l  = smu + SM_W2L;
    float* dred = (float*)(smu + SM_DRED);
    u16*   rp   = (u16*)(smu + SM_RP);   // [s][16][72]

    const int b = blockIdx.x, tid = threadIdx.x;
    const int wid = tid >> 5, lane = tid & 31;
    const int gid = lane >> 2, tig = lane & 3;
    const int nf = wid & 7, kh = wid >> 3;

    // ---- pack W1 (A-frag order: [kf][lane][4]) ----
    for (int e = tid; e < 8192; e += 512) {
        int kf = e >> 7, ln = (e >> 2) & 31, reg = e & 3;
        int row_l = (ln >> 2) + 8 * (reg & 1);
        int kc    = 16 * kf + 2 * (ln & 3) + 8 * (reg >> 1);
        const float* Ws = (b < 64)
            ? (Wmh + (size_t)(16 * b + row_l) * DIM)
            : (Wmm + (size_t)(16 * (b - 64) + row_l) * DIM);
        float w0 = Ws[kc], w1 = Ws[kc + 1];
        w1h[e] = packhi(w0, w1);
        w1l[e] = packlo(w0, w1);
    }
    // ---- pack W2: rows 16*(b>>1), k-half (b&1) ----
    for (int e = tid; e < 4096; e += 512) {
        int kfl = e >> 7, ln = (e >> 2) & 31, reg = e & 3;
        int row_g = 16 * (b >> 1) + (ln >> 2) + 8 * (reg & 1);
        int kc    = 512 * (b & 1) + 16 * kfl + 2 * (ln & 3) + 8 * (reg >> 1);
        float w0 = Whm[(size_t)row_g * DIM + kc];
        float w1 = Whm[(size_t)row_g * DIM + kc + 1];
        w2h[e] = packhi(w0, w1);
        w2l[e] = packlo(w0, w1);
    }
    __syncthreads();

    const int n0 = 8 * nf + 2 * tig;

    #pragma unroll 1
    for (int t = 0; t < T_STEPS; ++t) {
        // ================= phase 1: D = W1 @ m^T (full K) ==================
        float c[4] = {0.f, 0.f, 0.f, 0.f};
        {
            const u32* bhp = g_pm + pk(0, nf, 16 * kh, lane);
            const u32* blp = g_pm + pk(1, nf, 16 * kh, lane);
            uint4 Bh = *(const uint4*)bhp;
            uint4 Bl = *(const uint4*)blp;
            #pragma unroll 2
            for (int p = 0; p < 16; ++p) {
                uint4 cBh = Bh, cBl = Bl;
                if (p < 15) {
                    Bh = *(const uint4*)(bhp + (p + 1) * 128);
                    Bl = *(const uint4*)(blp + (p + 1) * 128);
                }
                int kf0 = 32 * kh + 2 * p;
                u32 Ah0[4], Ah1[4], Al0[4], Al1[4];
                *(uint4*)Ah0 = *(const uint4*)(w1h + ((size_t)kf0 * 32 + lane) * 4);
                *(uint4*)Ah1 = *(const uint4*)(w1h + ((size_t)(kf0 + 1) * 32 + lane) * 4);
                *(uint4*)Al0 = *(const uint4*)(w1l + ((size_t)kf0 * 32 + lane) * 4);
                *(uint4*)Al1 = *(const uint4*)(w1l + ((size_t)(kf0 + 1) * 32 + lane) * 4);
                mma4(c, Ah0, cBh.x, cBh.y);
                mma4(c, Ah0, cBl.x, cBl.y);
                mma4(c, Al0, cBh.x, cBh.y);
                mma4(c, Ah1, cBh.z, cBh.w);
                mma4(c, Ah1, cBl.z, cBl.w);
                mma4(c, Al1, cBh.z, cBh.w);
            }
        }
        // cross-k-half reduce through smem
        if (wid >= 8)
            *(float4*)&dred[(size_t)((wid - 8) * 32 + lane) * 4] = *(float4*)c;
        __syncthreads();
        if (wid < 8) {
            float4 o = *(float4*)&dred[(size_t)(wid * 32 + lane) * 4];
            c[0] += o.x; c[1] += o.y; c[2] += o.z; c[3] += o.w;
            if (b < 64) {
                int f0 = 16 * b + gid;
                ull xa = *(const ull*)(g_xWT + (size_t)t * STEP
                                       + (size_t)f0 * 64 + n0);
                ull xb = *(const ull*)(g_xWT + (size_t)t * STEP
                                       + (size_t)(f0 + 8) * 64 + n0);
                float h0 = tanhf(c[0] + __uint_as_float((u32)xa));
                float h1 = tanhf(c[1] + __uint_as_float((u32)(xa >> 32)));
                float h2 = tanhf(c[2] + __uint_as_float((u32)xb));
                float h3 = tanhf(c[3] + __uint_as_float((u32)(xb >> 32)));
                // rp[s][k][n] u16, row stride 72
                *(u32*)&rp[(0 * 16 + gid)     * 72 + n0] = packhi(h0, h1);
                *(u32*)&rp[(0 * 16 + gid + 8) * 72 + n0] = packhi(h2, h3);
                *(u32*)&rp[(1 * 16 + gid)     * 72 + n0] = packlo(h0, h1);
                *(u32*)&rp[(1 * 16 + gid + 8) * 72 + n0] = packlo(h2, h3);
            } else {
                int f0 = 16 * (b - 64) + gid;
                *(float2*)(g_c2 + (size_t)f0 * 64 + n0)       =
                    make_float2(c[0], c[1]);
                *(float2*)(g_c2 + (size_t)(f0 + 8) * 64 + n0) =
                    make_float2(c[2], c[3]);
            }
        }
        __syncthreads();
        if (b < 64) {            // repack h -> g_ph (B-frag layout), kf = b
            int s  = tid >> 8, q8 = tid & 255;
            int nf2 = q8 >> 5, ln2 = q8 & 31;
            int np = 8 * nf2 + (ln2 >> 2), tg = ln2 & 3;
            u32 v0 = (u32)rp[(s * 16 + 2 * tg)     * 72 + np]
                   | ((u32)rp[(s * 16 + 2 * tg + 1) * 72 + np] << 16);
            u32 v1 = (u32)rp[(s * 16 + 2 * tg + 8) * 72 + np]
                   | ((u32)rp[(s * 16 + 2 * tg + 9) * 72 + np] << 16);
            ull V = (ull)v0 | ((ull)v1 << 32);
            *(ull*)&g_ph[pk(s, nf2, b >> 1, ln2) + (size_t)(b & 1) * 2] = V;
        }
        bar_arrive_seq(b, 3 * t + 1);
        bar_wait_seq(3 * t + 1);

        // ================= phase 2: D = W2 @ h^T (K-half) ==================
        float d2[4] = {0.f, 0.f, 0.f, 0.f};
        {
            int pg0 = 16 * (b & 1) + 8 * kh;
            const u32* bhp = g_ph + pk(0, nf, pg0, lane);
            const u32* blp = g_ph + pk(1, nf, pg0, lane);
            uint4 Bh = *(const uint4*)bhp;
            uint4 Bl = *(const uint4*)blp;
            #pragma unroll 2
            for (int p = 0; p < 8; ++p) {
                uint4 cBh = Bh, cBl = Bl;
                if (p < 7) {
                    Bh = *(const uint4*)(bhp + (p + 1) * 128);
                    Bl = *(const uint4*)(blp + (p + 1) * 128);
                }
                int kfl0 = 16 * kh + 2 * p;
                u32 Ah0[4], Ah1[4], Al0[4], Al1[4];
                *(uint4*)Ah0 = *(const uint4*)(w2h + ((size_t)kfl0 * 32 + lane) * 4);
                *(uint4*)Ah1 = *(const uint4*)(w2h + ((size_t)(kfl0 + 1) * 32 + lane) * 4);
                *(uint4*)Al0 = *(const uint4*)(w2l + ((size_t)kfl0 * 32 + lane) * 4);
                *(uint4*)Al1 = *(const uint4*)(w2l + ((size_t)(kfl0 + 1) * 32 + lane) * 4);
                mma4(d2, Ah0, cBh.x, cBh.y);
                mma4(d2, Ah0, cBl.x, cBl.y);
                mma4(d2, Al0, cBh.x, cBh.y);
                mma4(d2, Ah1, cBh.z, cBh.w);
                mma4(d2, Ah1, cBl.z, cBl.w);
                mma4(d2, Al1, cBh.z, cBh.w);
            }
        }
        if (wid >= 8)
            *(float4*)&dred[(size_t)((wid - 8) * 32 + lane) * 4] = *(float4*)d2;
        __syncthreads();
        if (wid < 8) {
            float4 o = *(float4*)&dred[(size_t)(wid * 32 + lane) * 4];
            d2[0] += o.x; d2[1] += o.y; d2[2] += o.z; d2[3] += o.w;
            float* gp = g_partB + (size_t)b * 1024;
            *(float2*)(gp + (size_t)gid * 64 + n0)       = make_float2(d2[0], d2[1]);
            *(float2*)(gp + (size_t)(gid + 8) * 64 + n0) = make_float2(d2[2], d2[3]);
        }
        bar_arrive_seq(b, 3 * t + 2);
        bar_wait_seq(3 * t + 2);

        // ================= reduce2: m'-rows 8b..8b+7 =======================
        if (tid < 256) {
            int tg2 = tid >> 6, n = tid & 63;
            int rr0 = 2 * tg2, rr1 = rr0 + 1;
            int j = b >> 1;
            int lr0 = 8 * (b & 1) + rr0, lr1 = lr0 + 1;
            int r0 = 8 * b + rr0, r1 = r0 + 1;
            float v0 = g_partB[(size_t)(2 * j) * 1024 + lr0 * 64 + n]
                     + g_partB[(size_t)(2 * j + 1) * 1024 + lr0 * 64 + n]
                     + g_c2[(size_t)r0 * 64 + n] + bm[r0];
            float v1 = g_partB[(size_t)(2 * j) * 1024 + lr1 * 64 + n]
                     + g_partB[(size_t)(2 * j + 1) * 1024 + lr1 * 64 + n]
                     + g_c2[(size_t)r1 * 64 + n] + bm[r1];
            *(float2*)(out + (size_t)t * STEP + (size_t)n * DIM + r0) =
                make_float2(v0, v1);
            if (t == T_STEPS - 1)
                *(float2*)(out + OUTS + (size_t)n * DIM + r0) =
                    make_float2(v0, v1);
            // packed m' write: kf = b>>1 -> pair = b>>2, q = ((b>>1)&1)*2 + (b&1)
            int ln2 = ((n & 7) << 2) | tg2, nf2 = n >> 3;
            size_t base = (size_t)((b >> 1) & 1) * 2 + (b & 1);
            g_pm[pk(0, nf2, b >> 2, ln2) + base] = packhi(v0, v1);
            g_pm[pk(1, nf2, b >> 2, ln2) + base] = packlo(v0, v1);
        }
        bar_arrive_seq(b, 3 * t + 3);
        bar_wait_seq(3 * t + 3);
    }
}

#define PRO_SMEM ((W16_F + RED16) * 4)      // 155648 B

extern "C" void kernel_launch(void* const* d_in, const int* in_sizes, int n_in,
                              void* d_out, int out_size)
{
    const float* x      = (const float*)d_in[0];
    const float* m_prev = (const float*)d_in[1];
    const float* Wxh    = (const float*)d_in[2];
    const float* Whm    = (const float*)d_in[3];
    const float* Wmm    = (const float*)d_in[4];
    const float* Wmh    = (const float*)d_in[5];
    const float* bh     = (const float*)d_in[6];
    const float* bm     = (const float*)d_in[7];
    float* out = (float*)d_out;

    cudaFuncSetAttribute(prologue_k,
                         cudaFuncAttributeMaxDynamicSharedMemorySize, PRO_SMEM);
    cudaFuncSetAttribute(recur_k,
                         cudaFuncAttributeMaxDynamicSharedMemorySize, TC_SMEM);

    float* d_gxT; cudaGetSymbolAddress((void**)&d_gxT, g_xT);

    zero_flags_k<<<1, 128>>>();
    transpose_k<<<dim3(16, 512), 256>>>(x, d_gxT);          // x -> g_xT
    conv_m0_k<<<128, 512>>>(m_prev);                        // m0 -> g_pm
    prologue_k<<<dim3(64, 64), 1024, PRO_SMEM>>>(Wxh, bh);  // -> g_xWT
    recur_k<<<128, 512, TC_SMEM>>>(Whm, Wmm, Wmh, bm, out);
}